// round 16
// baseline (speedup 1.0000x reference)
#include <cuda_runtime.h>
#include <cuda_bf16.h>
#include <cstdint>

#define BATCHN 256
#define SEQLEN 512
#define NEMB   300
#define NHID   256
#define EMBS   320          // padded K (5 chunks of 64)
#define M_PAD  50304        // vocab rows padded to 128

typedef unsigned long long ull;

// ---------- packed f32x2 helpers (rnn path) ----------
__device__ __forceinline__ void fma2(ull &d, ull a, ull b) {
    asm("fma.rn.f32x2 %0, %1, %2, %0;" : "+l"(d) : "l"(a), "l"(b));
}
__device__ __forceinline__ ull pack2(float x, float y) {
    ull r; asm("mov.b64 %0, {%1, %2};" : "=l"(r) : "f"(x), "f"(y)); return r;
}
__device__ __forceinline__ float2 unpack2(ull v) {
    float2 r; asm("mov.b64 {%0, %1}, %2;" : "=f"(r.x), "=f"(r.y) : "l"(v)); return r;
}
__device__ __forceinline__ float sigmoidf(float z) {
    return 1.0f / (1.0f + __expf(-z));
}

// ---------- HMMA / ldmatrix / cp.async helpers ----------
__device__ __forceinline__ uint32_t smem_u32(const void* p) {
    uint32_t a;
    asm("{ .reg .u64 t; cvta.to.shared.u64 t, %1; cvt.u32.u64 %0, t; }" : "=r"(a) : "l"(p));
    return a;
}
__device__ __forceinline__ void ldm4(uint32_t* r, uint32_t addr) {
    asm volatile("ldmatrix.sync.aligned.m8n8.x4.shared.b16 {%0,%1,%2,%3}, [%4];"
                 : "=r"(r[0]), "=r"(r[1]), "=r"(r[2]), "=r"(r[3]) : "r"(addr));
}
__device__ __forceinline__ void mma16816(float* d, const uint32_t* a, uint32_t b0, uint32_t b1) {
    asm volatile(
        "mma.sync.aligned.m16n8k16.row.col.f32.bf16.bf16.f32 "
        "{%0,%1,%2,%3}, {%4,%5,%6,%7}, {%8,%9}, {%0,%1,%2,%3};"
        : "+f"(d[0]), "+f"(d[1]), "+f"(d[2]), "+f"(d[3])
        : "r"(a[0]), "r"(a[1]), "r"(a[2]), "r"(a[3]), "r"(b0), "r"(b1));
}
__device__ __forceinline__ uint32_t bfpair(float a, float b) {
    __nv_bfloat162 t = __floats2bfloat162_rn(a, b);
    return *(uint32_t*)&t;
}
__device__ __forceinline__ void sts128(uint32_t addr, uint4 v) {
    asm volatile("st.shared.v4.b32 [%0], {%1,%2,%3,%4};"
                 :: "r"(addr), "r"(v.x), "r"(v.y), "r"(v.z), "r"(v.w) : "memory");
}
#define CP16(dst, src) asm volatile("cp.async.cg.shared.global [%0], [%1], 16;" :: "r"(dst), "l"(src) : "memory")
#define CPCOMMIT()     asm volatile("cp.async.commit_group;" ::: "memory")
#define CPWAIT1()      asm volatile("cp.async.wait_group 1;" ::: "memory")
#define CPWAIT0()      asm volatile("cp.async.wait_group 0;" ::: "memory")

// ---------- device scratch ----------
__device__ float g_proj[(size_t)M_PAD * NHID];                // 51.5 MB: proj = emb @ Wi
__device__ __nv_bfloat16 g_wt_hi[256 * EMBS];                 // Wi^T hi  [n][k]
__device__ __nv_bfloat16 g_wt_lo[256 * EMBS];                 // Wi^T lo  [n][k]

// =====================================================================
// Wi^T split-convert: fp32 -> (hi, lo) bf16, K zero-padded to 320.
// =====================================================================
__global__ __launch_bounds__(128) void convert_wi_kernel(const float* __restrict__ Wi)
{
    const int n = blockIdx.x, tid = threadIdx.x;
    for (int k = tid; k < EMBS; k += 128) {
        float v = (k < NEMB) ? Wi[k * NHID + n] : 0.f;
        __nv_bfloat16 h = __float2bfloat16(v);
        g_wt_hi[n * EMBS + k] = h;
        g_wt_lo[n * EMBS + k] = __float2bfloat16(v - __bfloat162float(h));
    }
}

// =====================================================================
// proj = emb @ Wi via 3-GEMM bf16 split on HMMA.
// v2: 256-thr CTAs, 128x64 tiles, OCCUPANCY 2 (2 CTAs/SM share pipes).
// A (emb) converted fp32->hi/lo on the fly; B (Wi^T) via cp.async
// double-buffer. Grid (4 col-blocks, 393 row-blocks) col-inner for A L2 reuse.
// smem/CTA = 2 x (A 36KB + B 18KB) = 110.6 KB.
// =====================================================================
#define RSTRIDE 144
#define AHI_OFF 0
#define ALO_OFF 18432
#define BHI_OFF 36864
#define BLO_OFF 46080
#define BUFSZ   55296
#define G8_SMEM (2 * BUFSZ + 64)

__global__ void __launch_bounds__(256, 2) proj_gemm(const float* __restrict__ emb)
{
    extern __shared__ __align__(16) char dsm[];
    const uint32_t smb = smem_u32(dsm);

    const int tid = threadIdx.x, wid = tid >> 5, lid = tid & 31;
    const int cbase = blockIdx.x * 64;     // col-block (0..3) — inner dim
    const int rbase = blockIdx.y * 128;    // row-block (0..392)

    // A staging: 2 threads per row; thread covers 32 k per chunk
    const int arow  = rbase + (tid >> 1);
    const int arowg = (arow < 50257) ? arow : 50256;
    const int aq    = (tid & 1) * 32;      // k offset within 64-chunk
    float4 af[8];

    auto lda = [&](int c) {
        #pragma unroll
        for (int i = 0; i < 8; i++) {
            int k = c * 64 + aq + i * 4;
            af[i] = (k < NEMB) ? *(const float4*)&emb[(size_t)arowg * NEMB + k]
                               : make_float4(0.f, 0.f, 0.f, 0.f);
        }
    };
    auto sta = [&](int buf) {
        uint32_t hw[16], lw[16];
        #pragma unroll
        for (int i = 0; i < 8; i++) {
            float4 f = af[i];
            __nv_bfloat16 hx = __float2bfloat16(f.x), hy = __float2bfloat16(f.y);
            __nv_bfloat16 hz = __float2bfloat16(f.z), hv = __float2bfloat16(f.w);
            hw[i * 2]     = bfpair(__bfloat162float(hx), __bfloat162float(hy));
            hw[i * 2 + 1] = bfpair(__bfloat162float(hz), __bfloat162float(hv));
            lw[i * 2]     = bfpair(f.x - __bfloat162float(hx), f.y - __bfloat162float(hy));
            lw[i * 2 + 1] = bfpair(f.z - __bfloat162float(hz), f.w - __bfloat162float(hv));
        }
        uint32_t doff = (uint32_t)((tid >> 1) * RSTRIDE + aq * 2);
        uint32_t base = smb + buf * BUFSZ;
        sts128(base + AHI_OFF + doff,      make_uint4(hw[0],  hw[1],  hw[2],  hw[3]));
        sts128(base + AHI_OFF + doff + 16, make_uint4(hw[4],  hw[5],  hw[6],  hw[7]));
        sts128(base + AHI_OFF + doff + 32, make_uint4(hw[8],  hw[9],  hw[10], hw[11]));
        sts128(base + AHI_OFF + doff + 48, make_uint4(hw[12], hw[13], hw[14], hw[15]));
        sts128(base + ALO_OFF + doff,      make_uint4(lw[0],  lw[1],  lw[2],  lw[3]));
        sts128(base + ALO_OFF + doff + 16, make_uint4(lw[4],  lw[5],  lw[6],  lw[7]));
        sts128(base + ALO_OFF + doff + 32, make_uint4(lw[8],  lw[9],  lw[10], lw[11]));
        sts128(base + ALO_OFF + doff + 48, make_uint4(lw[12], lw[13], lw[14], lw[15]));
    };
    auto issueB = [&](int c, int buf) {
        const uint32_t base = smb + buf * BUFSZ;
        #pragma unroll
        for (int q = 0; q < 2; q++) {
            int idx = tid + q * 256;            // 0..511: 64 rows x 8 segs
            int row = idx >> 3, seg = idx & 7;
            uint32_t doff = (uint32_t)(row * RSTRIDE + seg * 16);
            size_t boff = (size_t)(cbase + row) * EMBS + c * 64 + seg * 8;
            CP16(base + BHI_OFF + doff, (const char*)(g_wt_hi + boff));
            CP16(base + BLO_OFF + doff, (const char*)(g_wt_lo + boff));
        }
        CPCOMMIT();
    };

    const int wm = (wid >> 1) * 32;   // 0..96
    const int wn = (wid & 1) * 32;    // 0 or 32
    const uint32_t a_lane =
        (uint32_t)((wm + (lid & 7) + ((lid >> 3) & 1) * 8) * RSTRIDE + ((lid >> 4) & 1) * 16);
    const uint32_t b_lane =
        (uint32_t)((wn + (lid & 7) + ((lid >> 4) & 1) * 8) * RSTRIDE + ((lid >> 3) & 1) * 16);

    float acc[2][4][4];
    #pragma unroll
    for (int m = 0; m < 2; m++)
        #pragma unroll
        for (int j = 0; j < 4; j++)
            #pragma unroll
            for (int e = 0; e < 4; e++) acc[m][j][e] = 0.f;

    lda(0);
    issueB(0, 0);

    for (int c = 0; c < 5; c++) {
        const int buf = c & 1;
        sta(buf);
        if (c + 1 < 5) {
            lda(c + 1);
            issueB(c + 1, buf ^ 1);
            CPWAIT1();
        } else {
            CPWAIT0();
        }
        __syncthreads();

        const uint32_t bb = smb + buf * BUFSZ;
        #pragma unroll
        for (int ks = 0; ks < 4; ks++) {
            const uint32_t ko = ks * 32;
            uint32_t ah[2][4], al[2][4], bh[2][4], bl[2][4];
            #pragma unroll
            for (int mt = 0; mt < 2; mt++) {
                ldm4(ah[mt], bb + AHI_OFF + a_lane + mt * (16 * RSTRIDE) + ko);
                ldm4(al[mt], bb + ALO_OFF + a_lane + mt * (16 * RSTRIDE) + ko);
            }
            #pragma unroll
            for (int np = 0; np < 2; np++) {
                ldm4(bh[np], bb + BHI_OFF + b_lane + np * (16 * RSTRIDE) + ko);
                ldm4(bl[np], bb + BLO_OFF + b_lane + np * (16 * RSTRIDE) + ko);
            }
            #pragma unroll
            for (int mt = 0; mt < 2; mt++)
                #pragma unroll
                for (int j = 0; j < 4; j++)
                    mma16816(acc[mt][j], ah[mt], bh[j >> 1][(j & 1) * 2], bh[j >> 1][(j & 1) * 2 + 1]);
            #pragma unroll
            for (int mt = 0; mt < 2; mt++)
                #pragma unroll
                for (int j = 0; j < 4; j++)
                    mma16816(acc[mt][j], al[mt], bh[j >> 1][(j & 1) * 2], bh[j >> 1][(j & 1) * 2 + 1]);
            #pragma unroll
            for (int mt = 0; mt < 2; mt++)
                #pragma unroll
                for (int j = 0; j < 4; j++)
                    mma16816(acc[mt][j], ah[mt], bl[j >> 1][(j & 1) * 2], bl[j >> 1][(j & 1) * 2 + 1]);
        }
        __syncthreads();
    }

    const int g  = lid >> 2;
    const int i2 = (lid & 3) * 2;
    #pragma unroll
    for (int mt = 0; mt < 2; mt++) {
        #pragma unroll
        for (int j = 0; j < 4; j++) {
            int row = rbase + wm + mt * 16 + g;
            int col = cbase + wn + j * 8 + i2;
            *(float2*)&g_proj[(size_t)row * NHID + col] =
                make_float2(acc[mt][j][0], acc[mt][j][1]);
            *(float2*)&g_proj[(size_t)(row + 8) * NHID + col] =
                make_float2(acc[mt][j][2], acc[mt][j][3]);
        }
    }
}

// =====================================================================
// Phase 2: 4-way intra-warp K-split recurrence (R15, unchanged).
// =====================================================================
#define SQ4 5
#define RQ4 11
#define WH4_BYTES (4 * SQ4 * 256 * 16)          // 80 KB
#define HB_OFF   WH4_BYTES
#define HQ       68
#define HROW     272
#define HBUF     544
#define WSM_OFF  (HB_OFF + 2 * HBUF * 4)
#define P2_SMEM  (WSM_OFF + 2 * 512 * 4)

__device__ __forceinline__ int hidx(int buf, int row, int col) {
    return buf * HBUF + row * HROW + (col >> 6) * HQ + (col & 63);
}

__global__ void __launch_bounds__(256, 1) rnn_kernel(
    const int* __restrict__ words,
    const float* __restrict__ Wh,
    const float* __restrict__ fcw,
    const float* __restrict__ fcb,
    float* __restrict__ out)
{
    extern __shared__ __align__(16) char smem[];
    ulonglong2* WhS = (ulonglong2*)smem;
    float*      hb  = (float*)(smem + HB_OFF);
    int*        wsm = (int*)(smem + WSM_OFF);

    const int tid  = threadIdx.x;
    const int w    = tid >> 5, lane = tid & 31;
    const int kh   = lane >> 3;
    const int cl   = lane & 7;
    const int cb   = 32 * w + cl;
    const int r0   = blockIdx.x * 2;

    for (int i = tid; i < 4 * SQ4 * 256; i += 256) {
        int qt  = i / (SQ4 * 256);
        int rem = i - qt * (SQ4 * 256);
        int q = rem >> 8, c = rem & 255;
        int kr = qt * 64 + 4 * q;
        float4 v = make_float4(Wh[kr * NHID + c],       Wh[(kr + 1) * NHID + c],
                               Wh[(kr + 2) * NHID + c], Wh[(kr + 3) * NHID + c]);
        ((float4*)smem)[i] = v;
    }
    for (int i = tid; i < SEQLEN; i += 256) {
        wsm[i]          = words[r0 * SEQLEN + i];
        wsm[SEQLEN + i] = words[(r0 + 1) * SEQLEN + i];
    }
    ulonglong2 whr[4][RQ4];
    #pragma unroll
    for (int ci = 0; ci < 4; ci++) {
        int c = cb + 8 * ci;
        #pragma unroll
        for (int q = 0; q < RQ4; q++) {
            int kr = kh * 64 + (SQ4 + q) * 4;
            whr[ci][q].x = pack2(Wh[kr * NHID + c],       Wh[(kr + 1) * NHID + c]);
            whr[ci][q].y = pack2(Wh[(kr + 2) * NHID + c], Wh[(kr + 3) * NHID + c]);
        }
    }
    hb[hidx(0, 0, tid)] = 0.f;
    hb[hidx(0, 1, tid)] = 0.f;
    __syncthreads();

    const int frow = kh & 1;
    const bool gsel = (kh & 2) != 0;
    const int cA   = cb + 16 * (kh >> 1);
    const int cB   = cA + 8;

    float xa = g_proj[(size_t)wsm[frow * SEQLEN] * NHID + cA];
    float xb = g_proj[(size_t)wsm[frow * SEQLEN] * NHID + cB];

    int buf = 0;
    for (int t = 0; t < SEQLEN; t++) {
        const ulonglong2* H0 =
            (const ulonglong2*)(hb + buf * HBUF + kh * HQ);
        const ulonglong2* H1 =
            (const ulonglong2*)(hb + buf * HBUF + HROW + kh * HQ);

        ull a0[4] = {0, 0, 0, 0};
        ull a1[4] = {0, 0, 0, 0};
        #pragma unroll
        for (int q = 0; q < SQ4; q++) {
            ulonglong2 h0 = H0[q];
            ulonglong2 h1 = H1[q];
            #pragma unroll
            for (int ci = 0; ci < 4; ci++) {
                ulonglong2 wv = WhS[(kh * SQ4 + q) * 256 + cb + 8 * ci];
                fma2(a0[ci], h0.x, wv.x); fma2(a0[ci], h0.y, wv.y);
                fma2(a1[ci], h1.x, wv.x); fma2(a1[ci], h1.y, wv.y);
            }
        }
        #pragma unroll
        for (int q = 0; q < RQ4; q++) {
            ulonglong2 h0 = H0[SQ4 + q];
            ulonglong2 h1 = H1[SQ4 + q];
            #pragma unroll
            for (int ci = 0; ci < 4; ci++) {
                fma2(a0[ci], h0.x, whr[ci][q].x); fma2(a0[ci], h0.y, whr[ci][q].y);
                fma2(a1[ci], h1.x, whr[ci][q].x); fma2(a1[ci], h1.y, whr[ci][q].y);
            }
        }

        float p0[4], p1[4];
        #pragma unroll
        for (int ci = 0; ci < 4; ci++) {
            float2 s0 = unpack2(a0[ci]);
            float2 s1 = unpack2(a1[ci]);
            p0[ci] = s0.x + s0.y;
            p1[ci] = s1.x + s1.y;
        }

        float mine[4];
        #pragma unroll
        for (int ci = 0; ci < 4; ci++) {
            float keep = frow ? p1[ci] : p0[ci];
            float send = frow ? p0[ci] : p1[ci];
            mine[ci] = keep + __shfl_xor_sync(0xffffffffu, send, 8);
        }
        float keep0 = gsel ? mine[2] : mine[0];
        float send0 = gsel ? mine[0] : mine[2];
        float keep1 = gsel ? mine[3] : mine[1];
        float send1 = gsel ? mine[1] : mine[3];
        float sa = keep0 + __shfl_xor_sync(0xffffffffu, send0, 16);
        float sb = keep1 + __shfl_xor_sync(0xffffffffu, send1, 16);

        float hna = sigmoidf(xa + sa);
        float hnb = sigmoidf(xb + sb);

        int nb = buf ^ 1;
        hb[hidx(nb, frow, cA)] = hna;
        hb[hidx(nb, frow, cB)] = hnb;

        if (t + 1 < SEQLEN) {
            size_t wrd = (size_t)wsm[frow * SEQLEN + t + 1] * NHID;
            xa = g_proj[wrd + cA];
            xb = g_proj[wrd + cB];
        }

        __syncthreads();
        buf = nb;
    }

    out[256 + r0 * NHID + tid]       = hb[hidx(buf, 0, tid)];
    out[256 + (r0 + 1) * NHID + tid] = hb[hidx(buf, 1, tid)];

    int ww = tid >> 5, l = tid & 31;
    if (ww < 2) {
        float s = 0.f;
        #pragma unroll
        for (int q = 0; q < 8; q++)
            s += hb[hidx(buf, ww, l + q * 32)] * fcw[l + q * 32];
        #pragma unroll
        for (int o = 16; o; o >>= 1)
            s += __shfl_xor_sync(0xffffffffu, s, o);
        if (l == 0)
            out[r0 + ww] = sigmoidf(s + fcb[0]);
    }
}

// =====================================================================
extern "C" void kernel_launch(void* const* d_in, const int* in_sizes, int n_in,
                              void* d_out, int out_size)
{
    const int*   words = (const int*)  d_in[0];
    const float* emb   = (const float*)d_in[1];
    const float* Wi    = (const float*)d_in[2];
    const float* Wh    = (const float*)d_in[3];
    const float* fcw   = (const float*)d_in[4];
    const float* fcb   = (const float*)d_in[5];
    float*       out   = (float*)d_out;

    cudaFuncSetAttribute(proj_gemm, cudaFuncAttributeMaxDynamicSharedMemorySize, G8_SMEM);
    cudaFuncSetAttribute(rnn_kernel, cudaFuncAttributeMaxDynamicSharedMemorySize, P2_SMEM);

    convert_wi_kernel<<<NHID, 128>>>(Wi);
    proj_gemm<<<dim3(NHID / 64, M_PAD / 128), 256, G8_SMEM>>>(emb);
    rnn_kernel<<<BATCHN / 2, 256, P2_SMEM>>>(words, Wh, fcw, fcb, out);
}

// round 17
// speedup vs baseline: 1.7514x; 1.7514x over previous
#include <cuda_runtime.h>
#include <cuda_bf16.h>
#include <cstdint>

#define BATCHN 256
#define SEQLEN 512
#define NEMB   300
#define NHID   256
#define EMBS   320          // padded K (5 chunks of 64)
#define M_PAD  50304        // vocab rows padded to 64/128

typedef unsigned long long ull;

// ---------- packed f32x2 helpers (rnn path) ----------
__device__ __forceinline__ void fma2(ull &d, ull a, ull b) {
    asm("fma.rn.f32x2 %0, %1, %2, %0;" : "+l"(d) : "l"(a), "l"(b));
}
__device__ __forceinline__ ull pack2(float x, float y) {
    ull r; asm("mov.b64 %0, {%1, %2};" : "=l"(r) : "f"(x), "f"(y)); return r;
}
__device__ __forceinline__ float2 unpack2(ull v) {
    float2 r; asm("mov.b64 {%0, %1}, %2;" : "=f"(r.x), "=f"(r.y) : "l"(v)); return r;
}
__device__ __forceinline__ float sigmoidf(float z) {
    return 1.0f / (1.0f + __expf(-z));
}

// ---------- HMMA / ldmatrix / cp.async helpers ----------
__device__ __forceinline__ uint32_t smem_u32(const void* p) {
    uint32_t a;
    asm("{ .reg .u64 t; cvta.to.shared.u64 t, %1; cvt.u32.u64 %0, t; }" : "=r"(a) : "l"(p));
    return a;
}
__device__ __forceinline__ void ldm4(uint32_t* r, uint32_t addr) {
    asm volatile("ldmatrix.sync.aligned.m8n8.x4.shared.b16 {%0,%1,%2,%3}, [%4];"
                 : "=r"(r[0]), "=r"(r[1]), "=r"(r[2]), "=r"(r[3]) : "r"(addr));
}
__device__ __forceinline__ void mma16816(float* d, const uint32_t* a, uint32_t b0, uint32_t b1) {
    asm volatile(
        "mma.sync.aligned.m16n8k16.row.col.f32.bf16.bf16.f32 "
        "{%0,%1,%2,%3}, {%4,%5,%6,%7}, {%8,%9}, {%0,%1,%2,%3};"
        : "+f"(d[0]), "+f"(d[1]), "+f"(d[2]), "+f"(d[3])
        : "r"(a[0]), "r"(a[1]), "r"(a[2]), "r"(a[3]), "r"(b0), "r"(b1));
}
__device__ __forceinline__ uint32_t bfpair(float a, float b) {
    __nv_bfloat162 t = __floats2bfloat162_rn(a, b);
    return *(uint32_t*)&t;
}
__device__ __forceinline__ void sts128(uint32_t addr, uint4 v) {
    asm volatile("st.shared.v4.b32 [%0], {%1,%2,%3,%4};"
                 :: "r"(addr), "r"(v.x), "r"(v.y), "r"(v.z), "r"(v.w) : "memory");
}
#define CP16(dst, src) asm volatile("cp.async.cg.shared.global [%0], [%1], 16;" :: "r"(dst), "l"(src) : "memory")
#define CPCOMMIT()     asm volatile("cp.async.commit_group;" ::: "memory")
#define CPWAIT1()      asm volatile("cp.async.wait_group 1;" ::: "memory")
#define CPWAIT0()      asm volatile("cp.async.wait_group 0;" ::: "memory")

// ---------- device scratch ----------
__device__ float g_proj[(size_t)M_PAD * NHID];                // 51.5 MB: proj = emb @ Wi
__device__ __nv_bfloat16 g_wt_hi[256 * EMBS];                 // Wi^T hi  [n][k]
__device__ __nv_bfloat16 g_wt_lo[256 * EMBS];                 // Wi^T lo  [n][k]

// =====================================================================
// Wi^T split-convert: fp32 -> (hi, lo) bf16, K zero-padded to 320.
// =====================================================================
__global__ __launch_bounds__(128) void convert_wi_kernel(const float* __restrict__ Wi)
{
    const int n = blockIdx.x, tid = threadIdx.x;
    for (int k = tid; k < EMBS; k += 128) {
        float v = (k < NEMB) ? Wi[k * NHID + n] : 0.f;
        __nv_bfloat16 h = __float2bfloat16(v);
        g_wt_hi[n * EMBS + k] = h;
        g_wt_lo[n * EMBS + k] = __float2bfloat16(v - __bfloat162float(h));
    }
}

// =====================================================================
// proj = emb @ Wi via 3-GEMM bf16 split on HMMA.
// v3: R8 per-thread code EXACTLY, tile M halved -> 64x128, 256 thr, occ 2.
// 8 warps as 2x4; warp tile 32x32; af[4] staging (16 regs) as in R8.
// smem/CTA = 2 x 55.3 KB = 110.6 KB -> 2 CTAs/SM.
// =====================================================================
#define RSTRIDE 144
#define AHI_OFF 0
#define ALO_OFF 9216
#define BHI_OFF 18432
#define BLO_OFF 36864
#define BUFSZ   55296
#define G8_SMEM (2 * BUFSZ + 64)

__global__ void __launch_bounds__(256, 2) proj_gemm(const float* __restrict__ emb)
{
    extern __shared__ __align__(16) char dsm[];
    const uint32_t smb = smem_u32(dsm);

    const int tid = threadIdx.x, wid = tid >> 5, lid = tid & 31;
    const int rbase = blockIdx.x * 64;
    const int cbase = blockIdx.y * 128;

    // A staging: 4 threads per row (identical to R8)
    const int arow  = rbase + (tid >> 2);
    const int arowg = (arow < 50257) ? arow : 50256;
    const int aq    = (tid & 3) * 16;
    float4 af[4];

    auto lda = [&](int c) {
        #pragma unroll
        for (int i = 0; i < 4; i++) {
            int k = c * 64 + aq + i * 4;
            af[i] = (k < NEMB) ? *(const float4*)&emb[(size_t)arowg * NEMB + k]
                               : make_float4(0.f, 0.f, 0.f, 0.f);
        }
    };
    auto sta = [&](int buf) {
        uint32_t hw[8], lw[8];
        #pragma unroll
        for (int i = 0; i < 4; i++) {
            float4 f = af[i];
            __nv_bfloat16 hx = __float2bfloat16(f.x), hy = __float2bfloat16(f.y);
            __nv_bfloat16 hz = __float2bfloat16(f.z), hv = __float2bfloat16(f.w);
            hw[i * 2]     = bfpair(__bfloat162float(hx), __bfloat162float(hy));
            hw[i * 2 + 1] = bfpair(__bfloat162float(hz), __bfloat162float(hv));
            lw[i * 2]     = bfpair(f.x - __bfloat162float(hx), f.y - __bfloat162float(hy));
            lw[i * 2 + 1] = bfpair(f.z - __bfloat162float(hz), f.w - __bfloat162float(hv));
        }
        uint32_t doff = (uint32_t)((tid >> 2) * RSTRIDE + aq * 2);
        uint32_t base = smb + buf * BUFSZ;
        sts128(base + AHI_OFF + doff,      make_uint4(hw[0], hw[1], hw[2], hw[3]));
        sts128(base + AHI_OFF + doff + 16, make_uint4(hw[4], hw[5], hw[6], hw[7]));
        sts128(base + ALO_OFF + doff,      make_uint4(lw[0], lw[1], lw[2], lw[3]));
        sts128(base + ALO_OFF + doff + 16, make_uint4(lw[4], lw[5], lw[6], lw[7]));
    };
    auto issueB = [&](int c, int buf) {
        const uint32_t base = smb + buf * BUFSZ;
        #pragma unroll
        for (int q = 0; q < 4; q++) {
            int idx = tid + q * 256;            // 0..1023: 128 rows x 8 segs
            int row = idx >> 3, seg = idx & 7;
            uint32_t doff = (uint32_t)(row * RSTRIDE + seg * 16);
            size_t boff = (size_t)(cbase + row) * EMBS + c * 64 + seg * 8;
            CP16(base + BHI_OFF + doff, (const char*)(g_wt_hi + boff));
            CP16(base + BLO_OFF + doff, (const char*)(g_wt_lo + boff));
        }
        CPCOMMIT();
    };

    const int wm = (wid >> 2) * 32;   // 0 or 32
    const int wn = (wid & 3) * 32;    // 0..96
    const uint32_t a_lane =
        (uint32_t)((wm + (lid & 7) + ((lid >> 3) & 1) * 8) * RSTRIDE + ((lid >> 4) & 1) * 16);
    const uint32_t b_lane =
        (uint32_t)((wn + (lid & 7) + ((lid >> 4) & 1) * 8) * RSTRIDE + ((lid >> 3) & 1) * 16);

    float acc[2][4][4];
    #pragma unroll
    for (int m = 0; m < 2; m++)
        #pragma unroll
        for (int j = 0; j < 4; j++)
            #pragma unroll
            for (int e = 0; e < 4; e++) acc[m][j][e] = 0.f;

    lda(0);
    issueB(0, 0);

    for (int c = 0; c < 5; c++) {
        const int buf = c & 1;
        sta(buf);
        if (c + 1 < 5) {
            lda(c + 1);
            issueB(c + 1, buf ^ 1);
            CPWAIT1();
        } else {
            CPWAIT0();
        }
        __syncthreads();

        const uint32_t bb = smb + buf * BUFSZ;
        #pragma unroll
        for (int ks = 0; ks < 4; ks++) {
            const uint32_t ko = ks * 32;
            uint32_t ah[2][4], al[2][4], bh[2][4], bl[2][4];
            #pragma unroll
            for (int mt = 0; mt < 2; mt++) {
                ldm4(ah[mt], bb + AHI_OFF + a_lane + mt * (16 * RSTRIDE) + ko);
                ldm4(al[mt], bb + ALO_OFF + a_lane + mt * (16 * RSTRIDE) + ko);
            }
            #pragma unroll
            for (int np = 0; np < 2; np++) {
                ldm4(bh[np], bb + BHI_OFF + b_lane + np * (16 * RSTRIDE) + ko);
                ldm4(bl[np], bb + BLO_OFF + b_lane + np * (16 * RSTRIDE) + ko);
            }
            #pragma unroll
            for (int mt = 0; mt < 2; mt++)
                #pragma unroll
                for (int j = 0; j < 4; j++)
                    mma16816(acc[mt][j], ah[mt], bh[j >> 1][(j & 1) * 2], bh[j >> 1][(j & 1) * 2 + 1]);
            #pragma unroll
            for (int mt = 0; mt < 2; mt++)
                #pragma unroll
                for (int j = 0; j < 4; j++)
                    mma16816(acc[mt][j], al[mt], bh[j >> 1][(j & 1) * 2], bh[j >> 1][(j & 1) * 2 + 1]);
            #pragma unroll
            for (int mt = 0; mt < 2; mt++)
                #pragma unroll
                for (int j = 0; j < 4; j++)
                    mma16816(acc[mt][j], ah[mt], bl[j >> 1][(j & 1) * 2], bl[j >> 1][(j & 1) * 2 + 1]);
        }
        __syncthreads();
    }

    const int g  = lid >> 2;
    const int i2 = (lid & 3) * 2;
    #pragma unroll
    for (int mt = 0; mt < 2; mt++) {
        #pragma unroll
        for (int j = 0; j < 4; j++) {
            int row = rbase + wm + mt * 16 + g;
            int col = cbase + wn + j * 8 + i2;
            *(float2*)&g_proj[(size_t)row * NHID + col] =
                make_float2(acc[mt][j][0], acc[mt][j][1]);
            *(float2*)&g_proj[(size_t)(row + 8) * NHID + col] =
                make_float2(acc[mt][j][2], acc[mt][j][3]);
        }
    }
}

// =====================================================================
// Phase 2: 4-way intra-warp K-split recurrence (R15, unchanged).
// =====================================================================
#define SQ4 5
#define RQ4 11
#define WH4_BYTES (4 * SQ4 * 256 * 16)          // 80 KB
#define HB_OFF   WH4_BYTES
#define HQ       68
#define HROW     272
#define HBUF     544
#define WSM_OFF  (HB_OFF + 2 * HBUF * 4)
#define P2_SMEM  (WSM_OFF + 2 * 512 * 4)

__device__ __forceinline__ int hidx(int buf, int row, int col) {
    return buf * HBUF + row * HROW + (col >> 6) * HQ + (col & 63);
}

__global__ void __launch_bounds__(256, 1) rnn_kernel(
    const int* __restrict__ words,
    const float* __restrict__ Wh,
    const float* __restrict__ fcw,
    const float* __restrict__ fcb,
    float* __restrict__ out)
{
    extern __shared__ __align__(16) char smem[];
    ulonglong2* WhS = (ulonglong2*)smem;
    float*      hb  = (float*)(smem + HB_OFF);
    int*        wsm = (int*)(smem + WSM_OFF);

    const int tid  = threadIdx.x;
    const int w    = tid >> 5, lane = tid & 31;
    const int kh   = lane >> 3;
    const int cl   = lane & 7;
    const int cb   = 32 * w + cl;
    const int r0   = blockIdx.x * 2;

    for (int i = tid; i < 4 * SQ4 * 256; i += 256) {
        int qt  = i / (SQ4 * 256);
        int rem = i - qt * (SQ4 * 256);
        int q = rem >> 8, c = rem & 255;
        int kr = qt * 64 + 4 * q;
        float4 v = make_float4(Wh[kr * NHID + c],       Wh[(kr + 1) * NHID + c],
                               Wh[(kr + 2) * NHID + c], Wh[(kr + 3) * NHID + c]);
        ((float4*)smem)[i] = v;
    }
    for (int i = tid; i < SEQLEN; i += 256) {
        wsm[i]          = words[r0 * SEQLEN + i];
        wsm[SEQLEN + i] = words[(r0 + 1) * SEQLEN + i];
    }
    ulonglong2 whr[4][RQ4];
    #pragma unroll
    for (int ci = 0; ci < 4; ci++) {
        int c = cb + 8 * ci;
        #pragma unroll
        for (int q = 0; q < RQ4; q++) {
            int kr = kh * 64 + (SQ4 + q) * 4;
            whr[ci][q].x = pack2(Wh[kr * NHID + c],       Wh[(kr + 1) * NHID + c]);
            whr[ci][q].y = pack2(Wh[(kr + 2) * NHID + c], Wh[(kr + 3) * NHID + c]);
        }
    }
    hb[hidx(0, 0, tid)] = 0.f;
    hb[hidx(0, 1, tid)] = 0.f;
    __syncthreads();

    const int frow = kh & 1;
    const bool gsel = (kh & 2) != 0;
    const int cA   = cb + 16 * (kh >> 1);
    const int cB   = cA + 8;

    float xa = g_proj[(size_t)wsm[frow * SEQLEN] * NHID + cA];
    float xb = g_proj[(size_t)wsm[frow * SEQLEN] * NHID + cB];

    int buf = 0;
    for (int t = 0; t < SEQLEN; t++) {
        const ulonglong2* H0 =
            (const ulonglong2*)(hb + buf * HBUF + kh * HQ);
        const ulonglong2* H1 =
            (const ulonglong2*)(hb + buf * HBUF + HROW + kh * HQ);

        ull a0[4] = {0, 0, 0, 0};
        ull a1[4] = {0, 0, 0, 0};
        #pragma unroll
        for (int q = 0; q < SQ4; q++) {
            ulonglong2 h0 = H0[q];
            ulonglong2 h1 = H1[q];
            #pragma unroll
            for (int ci = 0; ci < 4; ci++) {
                ulonglong2 wv = WhS[(kh * SQ4 + q) * 256 + cb + 8 * ci];
                fma2(a0[ci], h0.x, wv.x); fma2(a0[ci], h0.y, wv.y);
                fma2(a1[ci], h1.x, wv.x); fma2(a1[ci], h1.y, wv.y);
            }
        }
        #pragma unroll
        for (int q = 0; q < RQ4; q++) {
            ulonglong2 h0 = H0[SQ4 + q];
            ulonglong2 h1 = H1[SQ4 + q];
            #pragma unroll
            for (int ci = 0; ci < 4; ci++) {
                fma2(a0[ci], h0.x, whr[ci][q].x); fma2(a0[ci], h0.y, whr[ci][q].y);
                fma2(a1[ci], h1.x, whr[ci][q].x); fma2(a1[ci], h1.y, whr[ci][q].y);
            }
        }

        float p0[4], p1[4];
        #pragma unroll
        for (int ci = 0; ci < 4; ci++) {
            float2 s0 = unpack2(a0[ci]);
            float2 s1 = unpack2(a1[ci]);
            p0[ci] = s0.x + s0.y;
            p1[ci] = s1.x + s1.y;
        }

        float mine[4];
        #pragma unroll
        for (int ci = 0; ci < 4; ci++) {
            float keep = frow ? p1[ci] : p0[ci];
            float send = frow ? p0[ci] : p1[ci];
            mine[ci] = keep + __shfl_xor_sync(0xffffffffu, send, 8);
        }
        float keep0 = gsel ? mine[2] : mine[0];
        float send0 = gsel ? mine[0] : mine[2];
        float keep1 = gsel ? mine[3] : mine[1];
        float send1 = gsel ? mine[1] : mine[3];
        float sa = keep0 + __shfl_xor_sync(0xffffffffu, send0, 16);
        float sb = keep1 + __shfl_xor_sync(0xffffffffu, send1, 16);

        float hna = sigmoidf(xa + sa);
        float hnb = sigmoidf(xb + sb);

        int nb = buf ^ 1;
        hb[hidx(nb, frow, cA)] = hna;
        hb[hidx(nb, frow, cB)] = hnb;

        if (t + 1 < SEQLEN) {
            size_t wrd = (size_t)wsm[frow * SEQLEN + t + 1] * NHID;
            xa = g_proj[wrd + cA];
            xb = g_proj[wrd + cB];
        }

        __syncthreads();
        buf = nb;
    }

    out[256 + r0 * NHID + tid]       = hb[hidx(buf, 0, tid)];
    out[256 + (r0 + 1) * NHID + tid] = hb[hidx(buf, 1, tid)];

    int ww = tid >> 5, l = tid & 31;
    if (ww < 2) {
        float s = 0.f;
        #pragma unroll
        for (int q = 0; q < 8; q++)
            s += hb[hidx(buf, ww, l + q * 32)] * fcw[l + q * 32];
        #pragma unroll
        for (int o = 16; o; o >>= 1)
            s += __shfl_xor_sync(0xffffffffu, s, o);
        if (l == 0)
            out[r0 + ww] = sigmoidf(s + fcb[0]);
    }
}

// =====================================================================
extern "C" void kernel_launch(void* const* d_in, const int* in_sizes, int n_in,
                              void* d_out, int out_size)
{
    const int*   words = (const int*)  d_in[0];
    const float* emb   = (const float*)d_in[1];
    const float* Wi    = (const float*)d_in[2];
    const float* Wh    = (const float*)d_in[3];
    const float* fcw   = (const float*)d_in[4];
    const float* fcb   = (const float*)d_in[5];
    float*       out   = (float*)d_out;

    cudaFuncSetAttribute(proj_gemm, cudaFuncAttributeMaxDynamicSharedMemorySize, G8_SMEM);
    cudaFuncSetAttribute(rnn_kernel, cudaFuncAttributeMaxDynamicSharedMemorySize, P2_SMEM);

    convert_wi_kernel<<<NHID, 128>>>(Wi);
    proj_gemm<<<dim3(M_PAD / 64, NHID / 128), 256, G8_SMEM>>>(emb);
    rnn_kernel<<<BATCHN / 2, 256, P2_SMEM>>>(words, Wh, fcw, fcb, out);
}